// round 1
// baseline (speedup 1.0000x reference)
#include <cuda_runtime.h>
#include <math.h>

#define L_SEQ 2048
#define BATCH 2
#define DMODEL 1024
#define NHEADS 16
#define DHEAD 64
#define TOKENS (BATCH * L_SEQ)

// ---------------- scratch (no allocations allowed -> __device__ globals) ----------------
__device__ float g_h[TOKENS * DMODEL];
__device__ float g_qkv[TOKENS * 3 * DMODEL];
__device__ float g_q[TOKENS * DMODEL];   // [B, H, L, 64]
__device__ float g_k[TOKENS * DMODEL];   // [B, H, L, 64]
__device__ float g_v[TOKENS * DMODEL];   // [B, H, L, 64]
__device__ float g_ctx[TOKENS * DMODEL]; // [B, L, D]
__device__ float g_cos[L_SEQ * 32];
__device__ float g_sin[L_SEQ * 32];

// ---------------- block reduction of 4 values (256 threads) ----------------
__device__ __forceinline__ void block_reduce4(float& a, float& b, float& c, float& d) {
    __shared__ float sbuf[8][4];
    int lane = threadIdx.x & 31, warp = threadIdx.x >> 5;
#pragma unroll
    for (int off = 16; off > 0; off >>= 1) {
        a += __shfl_down_sync(0xffffffffu, a, off);
        b += __shfl_down_sync(0xffffffffu, b, off);
        c += __shfl_down_sync(0xffffffffu, c, off);
        d += __shfl_down_sync(0xffffffffu, d, off);
    }
    if (lane == 0) { sbuf[warp][0] = a; sbuf[warp][1] = b; sbuf[warp][2] = c; sbuf[warp][3] = d; }
    __syncthreads();
    if (warp == 0) {
        a = lane < 8 ? sbuf[lane][0] : 0.f;
        b = lane < 8 ? sbuf[lane][1] : 0.f;
        c = lane < 8 ? sbuf[lane][2] : 0.f;
        d = lane < 8 ? sbuf[lane][3] : 0.f;
#pragma unroll
        for (int off = 4; off > 0; off >>= 1) {
            a += __shfl_down_sync(0xffffffffu, a, off);
            b += __shfl_down_sync(0xffffffffu, b, off);
            c += __shfl_down_sync(0xffffffffu, c, off);
            d += __shfl_down_sync(0xffffffffu, d, off);
        }
        if (lane == 0) { sbuf[0][0] = a; sbuf[0][1] = b; sbuf[0][2] = c; sbuf[0][3] = d; }
    }
    __syncthreads();
    a = sbuf[0][0]; b = sbuf[0][1]; c = sbuf[0][2]; d = sbuf[0][3];
}

// ---------------- RoPE table (double trig for accuracy; 65536 entries, trivial cost) ----
__global__ void rope_table_kernel() {
    int idx = blockIdx.x * blockDim.x + threadIdx.x;
    if (idx >= L_SEQ * 32) return;
    int l = idx >> 5, i = idx & 31;
    float invf = (float)pow(10000.0, -(double)(2 * i) / 64.0);
    float ang = (float)l * invf;  // matches jnp fp32 rounding of t*inv_freq
    g_cos[idx] = (float)cos((double)ang);
    g_sin[idx] = (float)sin((double)ang);
}

// ---------------- LN1: per token ----------------
__global__ __launch_bounds__(256) void ln1_kernel(const float* __restrict__ x,
                                                  const float* __restrict__ w,
                                                  const float* __restrict__ bvec) {
    int t = blockIdx.x;
    const float* xr = x + (size_t)t * DMODEL;
    float v[4];
    float s = 0.f, ss = 0.f, z0 = 0.f, z1 = 0.f;
#pragma unroll
    for (int i = 0; i < 4; i++) {
        v[i] = xr[i * 256 + threadIdx.x];
        s += v[i];
        ss += v[i] * v[i];
    }
    block_reduce4(s, ss, z0, z1);
    float mu = s * (1.f / DMODEL);
    float var = ss * (1.f / DMODEL) - mu * mu;
    float rs = rsqrtf(var + 1e-5f);
    float* hr = g_h + (size_t)t * DMODEL;
#pragma unroll
    for (int i = 0; i < 4; i++) {
        int d = i * 256 + threadIdx.x;
        hr[d] = (v[i] - mu) * rs * w[d] + bvec[d];
    }
}

// ---------------- Q/K LN + RoPE + transpose to [B,H,L,64]; copy V ----------------
__global__ __launch_bounds__(256) void qk_ln_rope_kernel(const float* __restrict__ qlw,
                                                         const float* __restrict__ klw) {
    __shared__ float qn[DMODEL];
    __shared__ float kn[DMODEL];
    int t = blockIdx.x;
    int b = t / L_SEQ, l = t % L_SEQ;
    const float* row = g_qkv + (size_t)t * 3 * DMODEL;
    float qv[4], kv[4];
    float sq = 0.f, sqq = 0.f, sk = 0.f, skk = 0.f;
#pragma unroll
    for (int i = 0; i < 4; i++) {
        int d = i * 256 + threadIdx.x;
        qv[i] = row[d];
        kv[i] = row[DMODEL + d];
        sq += qv[i]; sqq += qv[i] * qv[i];
        sk += kv[i]; skk += kv[i] * kv[i];
    }
    block_reduce4(sq, sqq, sk, skk);
    float muq = sq * (1.f / DMODEL);
    float varq = sqq * (1.f / DMODEL) - muq * muq;
    float rq = rsqrtf(varq + 1e-5f);
    float muk = sk * (1.f / DMODEL);
    float vark = skk * (1.f / DMODEL) - muk * muk;
    float rk = rsqrtf(vark + 1e-5f);
#pragma unroll
    for (int i = 0; i < 4; i++) {
        int d = i * 256 + threadIdx.x;
        qn[d] = (qv[i] - muq) * rq * qlw[d];
        kn[d] = (kv[i] - muk) * rk * klw[d];
    }
    __syncthreads();
#pragma unroll
    for (int i = 0; i < 4; i++) {
        int d = i * 256 + threadIdx.x;
        int hh = d >> 6, dd = d & 63, fi = dd & 31;
        float c = g_cos[l * 32 + fi];
        float sn = g_sin[l * 32 + fi];
        float qrot = (dd < 32) ? -qn[(hh << 6) + dd + 32] : qn[(hh << 6) + dd - 32];
        float krot = (dd < 32) ? -kn[(hh << 6) + dd + 32] : kn[(hh << 6) + dd - 32];
        size_t oidx = (((size_t)b * NHEADS + hh) * L_SEQ + l) * DHEAD + dd;
        g_q[oidx] = qn[d] * c + qrot * sn;
        g_k[oidx] = kn[d] * c + krot * sn;
        g_v[oidx] = row[2 * DMODEL + d];
    }
}

// ---------------- fp32 SGEMM, 128x128x8 tile, 8x8 per thread ----------------
__global__ __launch_bounds__(256) void sgemm_kernel(const float* __restrict__ A,
                                                    const float* __restrict__ B,
                                                    float* __restrict__ C,
                                                    int M, int N, int K) {
    __shared__ float As[8][128];
    __shared__ float Bs[8][128];
    int tid = threadIdx.x;
    int row0 = blockIdx.y * 128, col0 = blockIdx.x * 128;
    int tx = tid & 15, ty = tid >> 4;
    int aRow = tid >> 1, aCol = (tid & 1) * 4;
    int bRow = tid >> 5, bCol = (tid & 31) * 4;
    const float* Aptr = A + (size_t)(row0 + aRow) * K + aCol;
    const float* Bptr = B + (size_t)bRow * N + col0 + bCol;

    float acc[8][8];
#pragma unroll
    for (int i = 0; i < 8; i++)
#pragma unroll
        for (int j = 0; j < 8; j++) acc[i][j] = 0.f;

    for (int kt = 0; kt < K; kt += 8) {
        float4 a4 = *(const float4*)(Aptr + kt);
        float4 b4 = *(const float4*)(Bptr + (size_t)kt * N);
        As[aCol + 0][aRow] = a4.x;
        As[aCol + 1][aRow] = a4.y;
        As[aCol + 2][aRow] = a4.z;
        As[aCol + 3][aRow] = a4.w;
        *(float4*)&Bs[bRow][bCol] = b4;
        __syncthreads();
#pragma unroll
        for (int k = 0; k < 8; k++) {
            float ar[8], br[8];
            *(float4*)(ar)     = *(const float4*)&As[k][ty * 8];
            *(float4*)(ar + 4) = *(const float4*)&As[k][ty * 8 + 4];
            *(float4*)(br)     = *(const float4*)&Bs[k][tx * 8];
            *(float4*)(br + 4) = *(const float4*)&Bs[k][tx * 8 + 4];
#pragma unroll
            for (int i = 0; i < 8; i++)
#pragma unroll
                for (int j = 0; j < 8; j++) acc[i][j] += ar[i] * br[j];
        }
        __syncthreads();
    }
#pragma unroll
    for (int i = 0; i < 8; i++) {
        float* cr = C + (size_t)(row0 + ty * 8 + i) * N + col0 + tx * 8;
        *(float4*)cr       = make_float4(acc[i][0], acc[i][1], acc[i][2], acc[i][3]);
        *(float4*)(cr + 4) = make_float4(acc[i][4], acc[i][5], acc[i][6], acc[i][7]);
    }
}

// ---------------- segment-masked flash attention: 1 thread = 1 query ----------------
__global__ __launch_bounds__(64) void attn_kernel(const int* __restrict__ seq_id) {
    __shared__ float kvS[64 * 64];   // K tile, then reused for V tile
    __shared__ float sS[64 * 65];    // scores, pitch 65 -> conflict free
    __shared__ int sidS[64];
    int qt = blockIdx.x, hh = blockIdx.y, b = blockIdx.z;
    int tid = threadIdx.x;
    size_t base = ((size_t)b * NHEADS + hh) * L_SEQ * DHEAD;
    const float* Qb = g_q + base;
    const float* Kb = g_k + base;
    const float* Vb = g_v + base;
    const int* sid = seq_id + b * L_SEQ;
    int q0 = qt * 64;
    int myq = q0 + tid;
    int sq = sid[myq];
    int qmin = sid[q0], qmax = sid[q0 + 63]; // sorted -> ends are min/max

    float q[64], o[64];
#pragma unroll
    for (int i = 0; i < 16; i++) {
        float4 f = *(const float4*)&Qb[(size_t)myq * 64 + i * 4];
        q[i * 4 + 0] = f.x * 0.125f;  // fold in 1/sqrt(64)
        q[i * 4 + 1] = f.y * 0.125f;
        q[i * 4 + 2] = f.z * 0.125f;
        q[i * 4 + 3] = f.w * 0.125f;
    }
#pragma unroll
    for (int d = 0; d < 64; d++) o[d] = 0.f;
    float m = -1e30f, lsum = 0.f;

    for (int kt = 0; kt < L_SEQ / 64; kt++) {
        int k0 = kt * 64;
        int kmin = sid[k0], kmax = sid[k0 + 63];
        if (kmin > qmax) break;     // sorted ids: nothing further can match
        if (kmax < qmin) continue;  // fully below this block's range
        __syncthreads();            // protect kvS reuse (uniform control flow)
        {
            const float4* src = (const float4*)&Kb[(size_t)k0 * 64];
            float4* dst = (float4*)kvS;
#pragma unroll
            for (int i = 0; i < 16; i++) dst[i * 64 + tid] = src[i * 64 + tid];
            sidS[tid] = sid[k0 + tid];
        }
        __syncthreads();
        // ---- score pass ----
        float mt = m;
#pragma unroll 4
        for (int k = 0; k < 64; k++) {
            const float* kr = &kvS[k * 64];
            float s0 = 0.f, s1 = 0.f, s2 = 0.f, s3 = 0.f;
#pragma unroll
            for (int i = 0; i < 16; i++) {
                float4 f = *(const float4*)&kr[i * 4];
                s0 += q[i * 4 + 0] * f.x;
                s1 += q[i * 4 + 1] * f.y;
                s2 += q[i * 4 + 2] * f.z;
                s3 += q[i * 4 + 3] * f.w;
            }
            float s = (s0 + s1) + (s2 + s3);
            if (sidS[k] != sq) s = -1e30f;
            sS[tid * 65 + k] = s;
            mt = fmaxf(mt, s);
        }
        float alpha = expf(m - mt);  // m==mt==-1e30 -> exp(0)=1, lsum/o stay 0: safe
        lsum *= alpha;
#pragma unroll
        for (int d = 0; d < 64; d++) o[d] *= alpha;
        m = mt;
        __syncthreads();
        {
            const float4* src = (const float4*)&Vb[(size_t)k0 * 64];
            float4* dst = (float4*)kvS;
#pragma unroll
            for (int i = 0; i < 16; i++) dst[i * 64 + tid] = src[i * 64 + tid];
        }
        __syncthreads();
        // ---- probability / accumulate pass (mask re-checked: never exp(-1e30 - (-1e30))) ----
#pragma unroll 2
        for (int k = 0; k < 64; k++) {
            float p = (sidS[k] == sq) ? expf(sS[tid * 65 + k] - mt) : 0.f;
            lsum += p;
            const float* vr = &kvS[k * 64];
#pragma unroll
            for (int i = 0; i < 16; i++) {
                float4 f = *(const float4*)&vr[i * 4];
                o[i * 4 + 0] += p * f.x;
                o[i * 4 + 1] += p * f.y;
                o[i * 4 + 2] += p * f.z;
                o[i * 4 + 3] += p * f.w;
            }
        }
    }
    float inv = 1.f / lsum;  // every query matches itself -> lsum > 0
    float* dst = g_ctx + ((size_t)b * L_SEQ + myq) * DMODEL + hh * DHEAD;
#pragma unroll
    for (int i = 0; i < 16; i++) {
        *(float4*)&dst[i * 4] = make_float4(o[i * 4 + 0] * inv, o[i * 4 + 1] * inv,
                                            o[i * 4 + 2] * inv, o[i * 4 + 3] * inv);
    }
}

// ---------------- launch ----------------
extern "C" void kernel_launch(void* const* d_in, const int* in_sizes, int n_in,
                              void* d_out, int out_size) {
    const float* x      = (const float*)d_in[0];
    const int*   seq_id = (const int*)d_in[1];
    const float* ln1_w  = (const float*)d_in[2];
    const float* ln1_b  = (const float*)d_in[3];
    const float* w_qkv  = (const float*)d_in[4];
    const float* q_ln_w = (const float*)d_in[5];
    const float* k_ln_w = (const float*)d_in[6];
    const float* w_out  = (const float*)d_in[7];
    float* out = (float*)d_out;
    (void)in_sizes; (void)n_in; (void)out_size;

    void *p_h = nullptr, *p_qkv = nullptr, *p_ctx = nullptr;
    cudaGetSymbolAddress(&p_h, g_h);
    cudaGetSymbolAddress(&p_qkv, g_qkv);
    cudaGetSymbolAddress(&p_ctx, g_ctx);

    rope_table_kernel<<<64, 1024>>>();
    ln1_kernel<<<TOKENS, 256>>>(x, ln1_w, ln1_b);
    {
        dim3 grid(3 * DMODEL / 128, TOKENS / 128);
        sgemm_kernel<<<grid, 256>>>((const float*)p_h, w_qkv, (float*)p_qkv,
                                    TOKENS, 3 * DMODEL, DMODEL);
    }
    qk_ln_rope_kernel<<<TOKENS, 256>>>(q_ln_w, k_ln_w);
    {
        dim3 grid(L_SEQ / 64, NHEADS, BATCH);
        attn_kernel<<<grid, 64>>>(seq_id);
    }
    {
        dim3 grid(DMODEL / 128, TOKENS / 128);
        sgemm_kernel<<<grid, 256>>>((const float*)p_ctx, w_out, out,
                                    TOKENS, DMODEL, DMODEL);
    }
}

// round 4
// speedup vs baseline: 1.3941x; 1.3941x over previous
#include <cuda_runtime.h>
#include <cuda_bf16.h>
#include <math.h>
#include <stdint.h>

#define L_SEQ 2048
#define BATCH 2
#define DMODEL 1024
#define NHEADS 16
#define DHEAD 64
#define TOKENS (BATCH * L_SEQ)
#define KP 3072            // extended K: [hi | hi | lo] x [hi | lo | hi]

// ---------------- scratch ----------------
__device__ __nv_bfloat16 g_hq[TOKENS * KP];          // A' for QKV gemm
__device__ __nv_bfloat16 g_wqkvp[3 * DMODEL * KP];   // B' [3072][3072]
__device__ __nv_bfloat16 g_cp[TOKENS * KP];          // A' for out gemm (ctx)
__device__ __nv_bfloat16 g_woutp[DMODEL * KP];       // B' [1024][3072]
__device__ float g_qkv[TOKENS * 3 * DMODEL];
__device__ float g_q[TOKENS * DMODEL];               // [B, H, L, 64]
__device__ float g_k[TOKENS * DMODEL];
__device__ float g_v[TOKENS * DMODEL];
__device__ float g_cos[L_SEQ * 32];
__device__ float g_sin[L_SEQ * 32];

// ---------------- PTX helpers ----------------
__device__ __forceinline__ uint32_t smem_u32(const void* p) {
    uint32_t a;
    asm("{ .reg .u64 t; cvta.to.shared.u64 t, %1; cvt.u32.u64 %0, t; }" : "=r"(a) : "l"(p));
    return a;
}
#define CP_ASYNC16(dst, src) \
    asm volatile("cp.async.cg.shared.global [%0], [%1], 16;" :: "r"(dst), "l"(src))
#define CP_COMMIT() asm volatile("cp.async.commit_group;" ::: "memory")
#define CP_WAIT(n)  asm volatile("cp.async.wait_group %0;" :: "n"(n) : "memory")

__device__ __forceinline__ void ldm_x4(uint32_t* r, uint32_t addr) {
    asm volatile("ldmatrix.sync.aligned.m8n8.x4.shared.b16 {%0,%1,%2,%3}, [%4];"
                 : "=r"(r[0]), "=r"(r[1]), "=r"(r[2]), "=r"(r[3]) : "r"(addr));
}
__device__ __forceinline__ void mma_bf16(float* c, const uint32_t* a, uint32_t b0, uint32_t b1) {
    asm volatile(
        "mma.sync.aligned.m16n8k16.row.col.f32.bf16.bf16.f32 "
        "{%0,%1,%2,%3}, {%4,%5,%6,%7}, {%8,%9}, {%0,%1,%2,%3};"
        : "+f"(c[0]), "+f"(c[1]), "+f"(c[2]), "+f"(c[3])
        : "r"(a[0]), "r"(a[1]), "r"(a[2]), "r"(a[3]), "r"(b0), "r"(b1));
}

// ---------------- block reduction of 4 values (256 threads) ----------------
__device__ __forceinline__ void block_reduce4(float& a, float& b, float& c, float& d) {
    __shared__ float sbuf[8][4];
    int lane = threadIdx.x & 31, warp = threadIdx.x >> 5;
#pragma unroll
    for (int off = 16; off > 0; off >>= 1) {
        a += __shfl_down_sync(0xffffffffu, a, off);
        b += __shfl_down_sync(0xffffffffu, b, off);
        c += __shfl_down_sync(0xffffffffu, c, off);
        d += __shfl_down_sync(0xffffffffu, d, off);
    }
    if (lane == 0) { sbuf[warp][0] = a; sbuf[warp][1] = b; sbuf[warp][2] = c; sbuf[warp][3] = d; }
    __syncthreads();
    if (warp == 0) {
        a = lane < 8 ? sbuf[lane][0] : 0.f;
        b = lane < 8 ? sbuf[lane][1] : 0.f;
        c = lane < 8 ? sbuf[lane][2] : 0.f;
        d = lane < 8 ? sbuf[lane][3] : 0.f;
#pragma unroll
        for (int off = 4; off > 0; off >>= 1) {
            a += __shfl_down_sync(0xffffffffu, a, off);
            b += __shfl_down_sync(0xffffffffu, b, off);
            c += __shfl_down_sync(0xffffffffu, c, off);
            d += __shfl_down_sync(0xffffffffu, d, off);
        }
        if (lane == 0) { sbuf[0][0] = a; sbuf[0][1] = b; sbuf[0][2] = c; sbuf[0][3] = d; }
    }
    __syncthreads();
    a = sbuf[0][0]; b = sbuf[0][1]; c = sbuf[0][2]; d = sbuf[0][3];
}

// ---------------- RoPE table ----------------
__global__ void rope_table_kernel() {
    int idx = blockIdx.x * blockDim.x + threadIdx.x;
    if (idx >= L_SEQ * 32) return;
    int l = idx >> 5, i = idx & 31;
    float invf = (float)pow(10000.0, -(double)(2 * i) / 64.0);
    float ang = (float)l * invf;
    g_cos[idx] = (float)cos((double)ang);
    g_sin[idx] = (float)sin((double)ang);
}

// ---------------- transpose + bf16 split: W[K][N] -> B'[N][KP] = [hi|lo|hi] ----------
__global__ __launch_bounds__(256) void transpose_split_kernel(const float* __restrict__ W,
                                                              __nv_bfloat16* __restrict__ Bp,
                                                              int N) {
    __shared__ float t[32][33];
    int n0 = blockIdx.x * 32, k0 = blockIdx.y * 32;
    int tx = threadIdx.x & 31, ty = threadIdx.x >> 5; // 32 x 8
#pragma unroll
    for (int j = 0; j < 4; j++)
        t[ty + 8 * j][tx] = W[(size_t)(k0 + ty + 8 * j) * N + n0 + tx];
    __syncthreads();
#pragma unroll
    for (int j = 0; j < 4; j++) {
        float v = t[tx][ty + 8 * j];
        __nv_bfloat16 hi = __float2bfloat16(v);
        __nv_bfloat16 lo = __float2bfloat16(v - __bfloat162float(hi));
        size_t r = (size_t)(n0 + ty + 8 * j) * KP + (k0 + tx);
        Bp[r] = hi;
        Bp[r + DMODEL] = lo;
        Bp[r + 2 * DMODEL] = hi;
    }
}

// ---------------- LN1 -> A'[t][KP] = [hi|hi|lo] ----------------
__global__ __launch_bounds__(256) void ln1_kernel(const float* __restrict__ x,
                                                  const float* __restrict__ w,
                                                  const float* __restrict__ bvec) {
    int t = blockIdx.x;
    const float* xr = x + (size_t)t * DMODEL;
    float v[4];
    float s = 0.f, ss = 0.f, z0 = 0.f, z1 = 0.f;
#pragma unroll
    for (int i = 0; i < 4; i++) {
        v[i] = xr[i * 256 + threadIdx.x];
        s += v[i];
        ss += v[i] * v[i];
    }
    block_reduce4(s, ss, z0, z1);
    float mu = s * (1.f / DMODEL);
    float var = ss * (1.f / DMODEL) - mu * mu;
    float rs = rsqrtf(var + 1e-5f);
#pragma unroll
    for (int i = 0; i < 4; i++) {
        int d = i * 256 + threadIdx.x;
        float h = (v[i] - mu) * rs * w[d] + bvec[d];
        __nv_bfloat16 hi = __float2bfloat16(h);
        __nv_bfloat16 lo = __float2bfloat16(h - __bfloat162float(hi));
        size_t r = (size_t)t * KP + d;
        g_hq[r] = hi;
        g_hq[r + DMODEL] = hi;
        g_hq[r + 2 * DMODEL] = lo;
    }
}

// ---------------- bf16 mma.sync GEMM: C[M][N] = A'[M][KP] * B'[N][KP]^T ------------
// 128x128 CTA tile, BK=64, 8 warps each 64x32, m16n8k16.
#define GBM 128
#define GBN 128
#define GBK 64
#define NCHUNK (KP / GBK)

__global__ __launch_bounds__(256)
void bf16_gemm_kernel(const __nv_bfloat16* __restrict__ A,
                      const __nv_bfloat16* __restrict__ B,
                      float* __restrict__ C, int N) {
    extern __shared__ char sm[];
    uint32_t sbase = smem_u32(sm);  // As: 0,16K ; Bs: 32K,48K
    int tid = threadIdx.x, wid = tid >> 5, lane = tid & 31;
    int m0 = blockIdx.y * GBM, n0 = blockIdx.x * GBN;
    const __nv_bfloat16* Ag = A + (size_t)m0 * KP;
    const __nv_bfloat16* Bg = B + (size_t)n0 * KP;
    int wm = (wid >> 2) * 64, wn = (wid & 3) * 32;

    float acc[4][4][4];
#pragma unroll
    for (int i = 0; i < 4; i++)
#pragma unroll
        for (int j = 0; j < 4; j++)
#pragma unroll
            for (int q = 0; q < 4; q++) acc[i][j][q] = 0.f;

#define LOAD_TILE(c, buf) do {                                                  \
        uint32_t as = sbase + (buf) * 16384u;                                   \
        uint32_t bs = sbase + 32768u + (buf) * 16384u;                          \
        const __nv_bfloat16* ag = Ag + (c) * GBK;                               \
        const __nv_bfloat16* bg = Bg + (c) * GBK;                               \
        _Pragma("unroll")                                                       \
        for (int it = 0; it < 4; it++) {                                        \
            int lin = tid + it * 256;                                           \
            int row = lin >> 3, c8 = lin & 7;                                   \
            uint32_t so = (uint32_t)(row * 128 + (((c8) ^ (row & 7)) * 16));    \
            CP_ASYNC16(as + so, (const char*)(ag + (size_t)row * KP) + c8 * 16);\
            CP_ASYNC16(bs + so, (const char*)(bg + (size_t)row * KP) + c8 * 16);\
        }                                                                       \
        CP_COMMIT();                                                            \
    } while (0)

    LOAD_TILE(0, 0);

    for (int c = 0; c < NCHUNK; c++) {
        int buf = c & 1;
        if (c + 1 < NCHUNK) {
            LOAD_TILE(c + 1, buf ^ 1);
            CP_WAIT(1);
        } else {
            CP_WAIT(0);
        }
        __syncthreads();
        uint32_t as = sbase + buf * 16384u;
        uint32_t bs = sbase + 32768u + buf * 16384u;
#pragma unroll
        for (int ks = 0; ks < 4; ks++) {
            uint32_t afr[4][4];
#pragma unroll
            for (int mi = 0; mi < 4; mi++) {
                int row = wm + mi * 16 + (lane & 15);
                int c8 = ks * 2 + (lane >> 4);
                ldm_x4(afr[mi], as + row * 128 + ((c8 ^ (row & 7)) * 16));
            }
            uint32_t bfr[2][4];
#pragma unroll
            for (int nb = 0; nb < 2; nb++) {
                int row = wn + nb * 16 + ((lane >> 4) & 1) * 8 + (lane & 7);
                int c8 = ks * 2 + ((lane >> 3) & 1);
                ldm_x4(bfr[nb], bs + row * 128 + ((c8 ^ (row & 7)) * 16));
            }
#pragma unroll
            for (int mi = 0; mi < 4; mi++)
#pragma unroll
                for (int ni = 0; ni < 4; ni++)
                    mma_bf16(acc[mi][ni], afr[mi],
                             bfr[ni >> 1][(ni & 1) * 2], bfr[ni >> 1][(ni & 1) * 2 + 1]);
        }
        __syncthreads();
    }

    // epilogue: thread holds rows (lane>>2, +8), cols 2*(lane&3)+{0,1} of each m16n8
    int r0 = m0 + wm + (lane >> 2);
    int c0 = n0 + wn + (lane & 3) * 2;
#pragma unroll
    for (int mi = 0; mi < 4; mi++) {
#pragma unroll
        for (int ni = 0; ni < 4; ni++) {
            float* p0 = C + (size_t)(r0 + mi * 16) * N + c0 + ni * 8;
            float* p1 = C + (size_t)(r0 + mi * 16 + 8) * N + c0 + ni * 8;
            *(float2*)p0 = make_float2(acc[mi][ni][0], acc[mi][ni][1]);
            *(float2*)p1 = make_float2(acc[mi][ni][2], acc[mi][ni][3]);
        }
    }
#undef LOAD_TILE
}

// ---------------- Q/K LN + RoPE + transpose to [B,H,L,64]; copy V ----------------
__global__ __launch_bounds__(256) void qk_ln_rope_kernel(const float* __restrict__ qlw,
                                                         const float* __restrict__ klw) {
    __shared__ float qn[DMODEL];
    __shared__ float kn[DMODEL];
    int t = blockIdx.x;
    int b = t / L_SEQ, l = t % L_SEQ;
    const float* row = g_qkv + (size_t)t * 3 * DMODEL;
    float qv[4], kv[4];
    float sq = 0.f, sqq = 0.f, sk = 0.f, skk = 0.f;
#pragma unroll
    for (int i = 0; i < 4; i++) {
        int d = i * 256 + threadIdx.x;
        qv[i] = row[d];
        kv[i] = row[DMODEL + d];
        sq += qv[i]; sqq += qv[i] * qv[i];
        sk += kv[i]; skk += kv[i] * kv[i];
    }
    block_reduce4(sq, sqq, sk, skk);
    float muq = sq * (1.f / DMODEL);
    float rq = rsqrtf(sqq * (1.f / DMODEL) - muq * muq + 1e-5f);
    float muk = sk * (1.f / DMODEL);
    float rk = rsqrtf(skk * (1.f / DMODEL) - muk * muk + 1e-5f);
#pragma unroll
    for (int i = 0; i < 4; i++) {
        int d = i * 256 + threadIdx.x;
        qn[d] = (qv[i] - muq) * rq * qlw[d];
        kn[d] = (kv[i] - muk) * rk * klw[d];
    }
    __syncthreads();
#pragma unroll
    for (int i = 0; i < 4; i++) {
        int d = i * 256 + threadIdx.x;
        int hh = d >> 6, dd = d & 63, fi = dd & 31;
        float c = g_cos[l * 32 + fi];
        float sn = g_sin[l * 32 + fi];
        float qrot = (dd < 32) ? -qn[(hh << 6) + dd + 32] : qn[(hh << 6) + dd - 32];
        float krot = (dd < 32) ? -kn[(hh << 6) + dd + 32] : kn[(hh << 6) + dd - 32];
        size_t oidx = (((size_t)b * NHEADS + hh) * L_SEQ + l) * DHEAD + dd;
        g_q[oidx] = qn[d] * c + qrot * sn;
        g_k[oidx] = kn[d] * c + krot * sn;
        g_v[oidx] = row[2 * DMODEL + d];
    }
}

// ---------------- segment-masked flash attention: 1 thread = 1 query ----------------
__global__ __launch_bounds__(64) void attn_kernel(const int* __restrict__ seq_id) {
    __shared__ float kvS[64 * 64];
    __shared__ float sS[64 * 65];
    __shared__ int sidS[64];
    int qt = blockIdx.x, hh = blockIdx.y, b = blockIdx.z;
    int tid = threadIdx.x;
    size_t base = ((size_t)b * NHEADS + hh) * L_SEQ * DHEAD;
    const float* Qb = g_q + base;
    const float* Kb = g_k + base;
    const float* Vb = g_v + base;
    const int* sid = seq_id + b * L_SEQ;
    int q0 = qt * 64;
    int myq = q0 + tid;
    int sq = sid[myq];
    int qmin = sid[q0], qmax = sid[q0 + 63];

    float q[64], o[64];
#pragma unroll
    for (int i = 0; i < 16; i++) {
        float4 f = *(const float4*)&Qb[(size_t)myq * 64 + i * 4];
        q[i * 4 + 0] = f.x * 0.125f;
        q[i * 4 + 1] = f.y * 0.125f;
        q[i * 4 + 2] = f.z * 0.125f;
        q[i * 4 + 3] = f.w * 0.125f;
    }
#pragma unroll
    for (int d = 0; d < 64; d++) o[d] = 0.f;
    float m = -1e30f, lsum = 0.f;

    for (int kt = 0; kt < L_SEQ / 64; kt++) {
        int k0 = kt * 64;
        int kmin = sid[k0], kmax = sid[k0 + 63];
        if (kmin > qmax) break;
        if (kmax < qmin) continue;
        __syncthreads();
        {
            const float4* src = (const float4*)&Kb[(size_t)k0 * 64];
            float4* dst = (float4*)kvS;
#pragma unroll
            for (int i = 0; i < 16; i++) dst[i * 64 + tid] = src[i * 64 + tid];
            sidS[tid] = sid[k0 + tid];
        }
        __syncthreads();
        float mt = m;
#pragma unroll 4
        for (int k = 0; k < 64; k++) {
            const float* kr = &kvS[k * 64];
            float s0 = 0.f, s1 = 0.f, s2 = 0.f, s3 = 0.f;
#pragma unroll
            for (int i = 0; i < 16; i++) {
                float4 f = *(const float4*)&kr[i * 4];
                s0 += q[i * 4 + 0] * f.x;
                s1 += q[i * 4 + 1] * f.y;
                s2 += q[i * 4 + 2] * f.z;
                s3 += q[i * 4 + 3] * f.w;
            }
            float s = (s0 + s1) + (s2 + s3);
            if (sidS[k] != sq) s = -1e30f;
            sS[tid * 65 + k] = s;
            mt = fmaxf(mt, s);
        }
        float alpha = expf(m - mt);
        lsum *= alpha;
#pragma unroll
        for (int d = 0; d < 64; d++) o[d] *= alpha;
        m = mt;
        __syncthreads();
        {
            const float4* src = (const float4*)&Vb[(size_t)k0 * 64];
            float4* dst = (float4*)kvS;
#pragma unroll
            for (int i = 0; i < 16; i++) dst[i * 64 + tid] = src[i * 64 + tid];
        }
        __syncthreads();
#pragma unroll 2
        for (int k = 0; k < 64; k++) {
            float p = (sidS[k] == sq) ? expf(sS[tid * 65 + k] - mt) : 0.f;
            lsum += p;
            const float* vr = &kvS[k * 64];
#pragma unroll
            for (int i = 0; i < 16; i++) {
                float4 f = *(const float4*)&vr[i * 4];
                o[i * 4 + 0] += p * f.x;
                o[i * 4 + 1] += p * f.y;
                o[i * 4 + 2] += p * f.z;
                o[i * 4 + 3] += p * f.w;
            }
        }
    }
    float inv = 1.f / lsum;
    size_t co = ((size_t)b * L_SEQ + myq) * KP + hh * DHEAD;
#pragma unroll
    for (int i = 0; i < 64; i++) {
        float v = o[i] * inv;
        __nv_bfloat16 hi = __float2bfloat16(v);
        __nv_bfloat16 lo = __float2bfloat16(v - __bfloat162float(hi));
        g_cp[co + i] = hi;
        g_cp[co + DMODEL + i] = hi;
        g_cp[co + 2 * DMODEL + i] = lo;
    }
}

// ---------------- launch ----------------
extern "C" void kernel_launch(void* const* d_in, const int* in_sizes, int n_in,
                              void* d_out, int out_size) {
    const float* x      = (const float*)d_in[0];
    const int*   seq_id = (const int*)d_in[1];
    const float* ln1_w  = (const float*)d_in[2];
    const float* ln1_b  = (const float*)d_in[3];
    const float* w_qkv  = (const float*)d_in[4];
    const float* q_ln_w = (const float*)d_in[5];
    const float* k_ln_w = (const float*)d_in[6];
    const float* w_out  = (const float*)d_in[7];
    float* out = (float*)d_out;
    (void)in_sizes; (void)n_in; (void)out_size;

    void *p_hq = nullptr, *p_wq = nullptr, *p_cp = nullptr, *p_wo = nullptr, *p_qkv = nullptr;
    cudaGetSymbolAddress(&p_hq, g_hq);
    cudaGetSymbolAddress(&p_wq, g_wqkvp);
    cudaGetSymbolAddress(&p_cp, g_cp);
    cudaGetSymbolAddress(&p_wo, g_woutp);
    cudaGetSymbolAddress(&p_qkv, g_qkv);

    static const int GEMM_SMEM = 64 * 1024;
    cudaFuncSetAttribute(bf16_gemm_kernel,
                         cudaFuncAttributeMaxDynamicSharedMemorySize, GEMM_SMEM);

    rope_table_kernel<<<64, 1024>>>();
    transpose_split_kernel<<<dim3(3 * DMODEL / 32, DMODEL / 32), 256>>>(
        w_qkv, (__nv_bfloat16*)p_wq, 3 * DMODEL);
    transpose_split_kernel<<<dim3(DMODEL / 32, DMODEL / 32), 256>>>(
        w_out, (__nv_bfloat16*)p_wo, DMODEL);
    ln1_kernel<<<TOKENS, 256>>>(x, ln1_w, ln1_b);

    // QKV GEMM: [4096,3072] = A'[4096,3072] x B'[3072,3072]^T
    bf16_gemm_kernel<<<dim3(3 * DMODEL / GBN, TOKENS / GBM), 256, GEMM_SMEM>>>(
        (const __nv_bfloat16*)p_hq, (const __nv_bfloat16*)p_wq, (float*)p_qkv, 3 * DMODEL);

    qk_ln_rope_kernel<<<TOKENS, 256>>>(q_ln_w, k_ln_w);
    attn_kernel<<<dim3(L_SEQ / 64, NHEADS, BATCH), 64>>>(seq_id);

    // Output GEMM: [4096,1024] = ctx'[4096,3072] x B'[1024,3072]^T
    bf16_gemm_kernel<<<dim3(DMODEL / GBN, TOKENS / GBM), 256, GEMM_SMEM>>>(
        (const __nv_bfloat16*)p_cp, (const __nv_bfloat16*)p_wo, out, DMODEL);
}

// round 9
// speedup vs baseline: 2.7312x; 1.9591x over previous
#include <cuda_runtime.h>
#include <cuda_bf16.h>
#include <math.h>
#include <stdint.h>

#define L_SEQ 2048
#define BATCH 2
#define DMODEL 1024
#define NHEADS 16
#define DHEAD 64
#define TOKENS (BATCH * L_SEQ)
#define KP 3072            // extended K: [hi | hi | lo] x [hi | lo | hi]
#define NBH (BATCH * NHEADS)

// ---------------- scratch ----------------
__device__ __nv_bfloat16 g_hq[TOKENS * KP];          // A' for QKV gemm
__device__ __nv_bfloat16 g_wqkvp[3 * DMODEL * KP];   // B' [3072][3072]
__device__ __nv_bfloat16 g_cp[TOKENS * KP];          // A' for out gemm (ctx)
__device__ __nv_bfloat16 g_woutp[DMODEL * KP];       // B' [1024][3072]
__device__ float g_qkv[TOKENS * 3 * DMODEL];
__device__ float g_v[TOKENS * DMODEL];               // [B, H, L, 64] fp32
__device__ __nv_bfloat16 g_qp[NBH * L_SEQ * 192];    // [bh][l][qh|qh|ql] (scaled)
__device__ __nv_bfloat16 g_kp[NBH * L_SEQ * 192];    // [bh][l][kh|kl|kh]
__device__ __nv_bfloat16 g_vth[NBH * DHEAD * L_SEQ]; // V^T hi [bh][d][l]
__device__ __nv_bfloat16 g_vtl[NBH * DHEAD * L_SEQ]; // V^T lo
__device__ float g_cos[L_SEQ * 32];
__device__ float g_sin[L_SEQ * 32];

// ---------------- PTX helpers ----------------
__device__ __forceinline__ uint32_t smem_u32(const void* p) {
    uint32_t a;
    asm("{ .reg .u64 t; cvta.to.shared.u64 t, %1; cvt.u32.u64 %0, t; }" : "=r"(a) : "l"(p));
    return a;
}
#define CP_ASYNC16(dst, src) \
    asm volatile("cp.async.cg.shared.global [%0], [%1], 16;" :: "r"(dst), "l"(src))
#define CP_COMMIT() asm volatile("cp.async.commit_group;" ::: "memory")
#define CP_WAIT(n)  asm volatile("cp.async.wait_group %0;" :: "n"(n) : "memory")

__device__ __forceinline__ void ldm_x4(uint32_t* r, uint32_t addr) {
    asm volatile("ldmatrix.sync.aligned.m8n8.x4.shared.b16 {%0,%1,%2,%3}, [%4];"
                 : "=r"(r[0]), "=r"(r[1]), "=r"(r[2]), "=r"(r[3]) : "r"(addr));
}
__device__ __forceinline__ void mma_bf16(float* c, const uint32_t* a, uint32_t b0, uint32_t b1) {
    asm volatile(
        "mma.sync.aligned.m16n8k16.row.col.f32.bf16.bf16.f32 "
        "{%0,%1,%2,%3}, {%4,%5,%6,%7}, {%8,%9}, {%0,%1,%2,%3};"
        : "+f"(c[0]), "+f"(c[1]), "+f"(c[2]), "+f"(c[3])
        : "r"(a[0]), "r"(a[1]), "r"(a[2]), "r"(a[3]), "r"(b0), "r"(b1));
}
__device__ __forceinline__ uint32_t pack_bf16(float a, float b) {
    __nv_bfloat162 h = __floats2bfloat162_rn(a, b);
    return *(uint32_t*)&h;
}

// ---------------- block reduction of 4 values (256 threads) ----------------
__device__ __forceinline__ void block_reduce4(float& a, float& b, float& c, float& d) {
    __shared__ float sbuf[8][4];
    int lane = threadIdx.x & 31, warp = threadIdx.x >> 5;
#pragma unroll
    for (int off = 16; off > 0; off >>= 1) {
        a += __shfl_down_sync(0xffffffffu, a, off);
        b += __shfl_down_sync(0xffffffffu, b, off);
        c += __shfl_down_sync(0xffffffffu, c, off);
        d += __shfl_down_sync(0xffffffffu, d, off);
    }
    if (lane == 0) { sbuf[warp][0] = a; sbuf[warp][1] = b; sbuf[warp][2] = c; sbuf[warp][3] = d; }
    __syncthreads();
    if (warp == 0) {
        a = lane < 8 ? sbuf[lane][0] : 0.f;
        b = lane < 8 ? sbuf[lane][1] : 0.f;
        c = lane < 8 ? sbuf[lane][2] : 0.f;
        d = lane < 8 ? sbuf[lane][3] : 0.f;
#pragma unroll
        for (int off = 4; off > 0; off >>= 1) {
            a += __shfl_down_sync(0xffffffffu, a, off);
            b += __shfl_down_sync(0xffffffffu, b, off);
            c += __shfl_down_sync(0xffffffffu, c, off);
            d += __shfl_down_sync(0xffffffffu, d, off);
        }
        if (lane == 0) { sbuf[0][0] = a; sbuf[0][1] = b; sbuf[0][2] = c; sbuf[0][3] = d; }
    }
    __syncthreads();
    a = sbuf[0][0]; b = sbuf[0][1]; c = sbuf[0][2]; d = sbuf[0][3];
}

// ---------------- RoPE table ----------------
__global__ void rope_table_kernel() {
    int idx = blockIdx.x * blockDim.x + threadIdx.x;
    if (idx >= L_SEQ * 32) return;
    int l = idx >> 5, i = idx & 31;
    float invf = (float)pow(10000.0, -(double)(2 * i) / 64.0);
    float ang = (float)l * invf;
    g_cos[idx] = (float)cos((double)ang);
    g_sin[idx] = (float)sin((double)ang);
}

// ---------------- transpose + bf16 split: W[K][N] -> B'[N][KP] = [hi|lo|hi] ----------
__global__ __launch_bounds__(256) void transpose_split_kernel(const float* __restrict__ W,
                                                              __nv_bfloat16* __restrict__ Bp,
                                                              int N) {
    __shared__ float t[32][33];
    int n0 = blockIdx.x * 32, k0 = blockIdx.y * 32;
    int tx = threadIdx.x & 31, ty = threadIdx.x >> 5; // 32 x 8
#pragma unroll
    for (int j = 0; j < 4; j++)
        t[ty + 8 * j][tx] = W[(size_t)(k0 + ty + 8 * j) * N + n0 + tx];
    __syncthreads();
#pragma unroll
    for (int j = 0; j < 4; j++) {
        float v = t[tx][ty + 8 * j];
        __nv_bfloat16 hi = __float2bfloat16(v);
        __nv_bfloat16 lo = __float2bfloat16(v - __bfloat162float(hi));
        size_t r = (size_t)(n0 + ty + 8 * j) * KP + (k0 + tx);
        Bp[r] = hi;
        Bp[r + DMODEL] = lo;
        Bp[r + 2 * DMODEL] = hi;
    }
}

// ---------------- LN1 -> A'[t][KP] = [hi|hi|lo] ----------------
__global__ __launch_bounds__(256) void ln1_kernel(const float* __restrict__ x,
                                                  const float* __restrict__ w,
                                                  const float* __restrict__ bvec) {
    int t = blockIdx.x;
    const float* xr = x + (size_t)t * DMODEL;
    float v[4];
    float s = 0.f, ss = 0.f, z0 = 0.f, z1 = 0.f;
#pragma unroll
    for (int i = 0; i < 4; i++) {
        v[i] = xr[i * 256 + threadIdx.x];
        s += v[i];
        ss += v[i] * v[i];
    }
    block_reduce4(s, ss, z0, z1);
    float mu = s * (1.f / DMODEL);
    float var = ss * (1.f / DMODEL) - mu * mu;
    float rs = rsqrtf(var + 1e-5f);
#pragma unroll
    for (int i = 0; i < 4; i++) {
        int d = i * 256 + threadIdx.x;
        float h = (v[i] - mu) * rs * w[d] + bvec[d];
        __nv_bfloat16 hi = __float2bfloat16(h);
        __nv_bfloat16 lo = __float2bfloat16(h - __bfloat162float(hi));
        size_t r = (size_t)t * KP + d;
        g_hq[r] = hi;
        g_hq[r + DMODEL] = hi;
        g_hq[r + 2 * DMODEL] = lo;
    }
}

// ---------------- bf16 mma.sync GEMM (proven R4) ----------------
#define GBM 128
#define GBN 128
#define GBK 64
#define NCHUNK (KP / GBK)

__global__ __launch_bounds__(256)
void bf16_gemm_kernel(const __nv_bfloat16* __restrict__ A,
                      const __nv_bfloat16* __restrict__ B,
                      float* __restrict__ C, int N) {
    extern __shared__ char sm[];
    uint32_t sbase = smem_u32(sm);
    int tid = threadIdx.x, wid = tid >> 5, lane = tid & 31;
    int m0 = blockIdx.y * GBM, n0 = blockIdx.x * GBN;
    const __nv_bfloat16* Ag = A + (size_t)m0 * KP;
    const __nv_bfloat16* Bg = B + (size_t)n0 * KP;
    int wm = (wid >> 2) * 64, wn = (wid & 3) * 32;

    float acc[4][4][4];
#pragma unroll
    for (int i = 0; i < 4; i++)
#pragma unroll
        for (int j = 0; j < 4; j++)
#pragma unroll
            for (int q = 0; q < 4; q++) acc[i][j][q] = 0.f;

#define LOAD_TILE(c, buf) do {                                                  \
        uint32_t as = sbase + (buf) * 16384u;                                   \
        uint32_t bs = sbase + 32768u + (buf) * 16384u;                          \
        const __nv_bfloat16* ag = Ag + (c) * GBK;                               \
        const __nv_bfloat16* bg = Bg + (c) * GBK;                               \
        _Pragma("unroll")                                                       \
        for (int it = 0; it < 4; it++) {                                        \
            int lin = tid + it * 256;                                           \
            int row = lin >> 3, c8 = lin & 7;                                   \
            uint32_t so = (uint32_t)(row * 128 + (((c8) ^ (row & 7)) * 16));    \
            CP_ASYNC16(as + so, (const char*)(ag + (size_t)row * KP) + c8 * 16);\
            CP_ASYNC16(bs + so, (const char*)(bg + (size_t)row * KP) + c8 * 16);\
        }                                                                       \
        CP_COMMIT();                                                            \
    } while (0)

    LOAD_TILE(0, 0);

    for (int c = 0; c < NCHUNK; c++) {
        int buf = c & 1;
        if (c + 1 < NCHUNK) {
            LOAD_TILE(c + 1, buf ^ 1);
            CP_WAIT(1);
        } else {
            CP_WAIT(0);
        }
        __syncthreads();
        uint32_t as = sbase + buf * 16384u;
        uint32_t bs = sbase + 32768u + buf * 16384u;
#pragma unroll
        for (int ks = 0; ks < 4; ks++) {
            uint32_t afr[4][4];
#pragma unroll
            for (int mi = 0; mi < 4; mi++) {
                int row = wm + mi * 16 + (lane & 15);
                int c8 = ks * 2 + (lane >> 4);
                ldm_x4(afr[mi], as + row * 128 + ((c8 ^ (row & 7)) * 16));
            }
            uint32_t bfr[2][4];
#pragma unroll
            for (int nb = 0; nb < 2; nb++) {
                int row = wn + nb * 16 + ((lane >> 4) & 1) * 8 + (lane & 7);
                int c8 = ks * 2 + ((lane >> 3) & 1);
                ldm_x4(bfr[nb], bs + row * 128 + ((c8 ^ (row & 7)) * 16));
            }
#pragma unroll
            for (int mi = 0; mi < 4; mi++)
#pragma unroll
                for (int ni = 0; ni < 4; ni++)
                    mma_bf16(acc[mi][ni], afr[mi],
                             bfr[ni >> 1][(ni & 1) * 2], bfr[ni >> 1][(ni & 1) * 2 + 1]);
        }
        __syncthreads();
    }

    int r0 = m0 + wm + (lane >> 2);
    int c0 = n0 + wn + (lane & 3) * 2;
#pragma unroll
    for (int mi = 0; mi < 4; mi++) {
#pragma unroll
        for (int ni = 0; ni < 4; ni++) {
            float* p0 = C + (size_t)(r0 + mi * 16) * N + c0 + ni * 8;
            float* p1 = C + (size_t)(r0 + mi * 16 + 8) * N + c0 + ni * 8;
            *(float2*)p0 = make_float2(acc[mi][ni][0], acc[mi][ni][1]);
            *(float2*)p1 = make_float2(acc[mi][ni][2], acc[mi][ni][3]);
        }
    }
#undef LOAD_TILE
}

// ---------------- Q/K LN + RoPE -> split bf16 Q'/K'; V fp32 ----------------
__global__ __launch_bounds__(256) void qk_ln_rope_kernel(const float* __restrict__ qlw,
                                                         const float* __restrict__ klw) {
    __shared__ float qn[DMODEL];
    __shared__ float kn[DMODEL];
    int t = blockIdx.x;
    int b = t / L_SEQ, l = t % L_SEQ;
    const float* row = g_qkv + (size_t)t * 3 * DMODEL;
    float qv[4], kv[4];
    float sq = 0.f, sqq = 0.f, sk = 0.f, skk = 0.f;
#pragma unroll
    for (int i = 0; i < 4; i++) {
        int d = i * 256 + threadIdx.x;
        qv[i] = row[d];
        kv[i] = row[DMODEL + d];
        sq += qv[i]; sqq += qv[i] * qv[i];
        sk += kv[i]; skk += kv[i] * kv[i];
    }
    block_reduce4(sq, sqq, sk, skk);
    float muq = sq * (1.f / DMODEL);
    float rq = rsqrtf(sqq * (1.f / DMODEL) - muq * muq + 1e-5f);
    float muk = sk * (1.f / DMODEL);
    float rk = rsqrtf(skk * (1.f / DMODEL) - muk * muk + 1e-5f);
#pragma unroll
    for (int i = 0; i < 4; i++) {
        int d = i * 256 + threadIdx.x;
        qn[d] = (qv[i] - muq) * rq * qlw[d];
        kn[d] = (kv[i] - muk) * rk * klw[d];
    }
    __syncthreads();
#pragma unroll
    for (int i = 0; i < 4; i++) {
        int d = i * 256 + threadIdx.x;
        int hh = d >> 6, dd = d & 63, fi = dd & 31;
        float c = g_cos[l * 32 + fi];
        float sn = g_sin[l * 32 + fi];
        float qrot = (dd < 32) ? -qn[(hh << 6) + dd + 32] : qn[(hh << 6) + dd - 32];
        float krot = (dd < 32) ? -kn[(hh << 6) + dd + 32] : kn[(hh << 6) + dd - 32];
        float qf = (qn[d] * c + qrot * sn) * 0.125f;  // fold 1/sqrt(64)
        float kf = kn[d] * c + krot * sn;
        int bh = b * NHEADS + hh;
        size_t qb = ((size_t)bh * L_SEQ + l) * 192 + dd;
        __nv_bfloat16 qh = __float2bfloat16(qf);
        __nv_bfloat16 ql = __float2bfloat16(qf - __bfloat162float(qh));
        g_qp[qb] = qh; g_qp[qb + 64] = qh; g_qp[qb + 128] = ql;
        __nv_bfloat16 kh = __float2bfloat16(kf);
        __nv_bfloat16 klo = __float2bfloat16(kf - __bfloat162float(kh));
        g_kp[qb] = kh; g_kp[qb + 64] = klo; g_kp[qb + 128] = kh;
        g_v[((size_t)bh * L_SEQ + l) * DHEAD + dd] = row[2 * DMODEL + d];
    }
}

// ---------------- V transpose: [bh][l][64] fp32 -> [bh][d][l] bf16 hi/lo ----------
__global__ __launch_bounds__(256) void vt_kernel() {
    __shared__ float t[64][65];
    int bh = blockIdx.y, l0 = blockIdx.x * 64;
    const float* src = g_v + ((size_t)bh * L_SEQ + l0) * DHEAD;
#pragma unroll
    for (int it = 0; it < 16; it++) {
        int lin = it * 256 + threadIdx.x;
        int r = lin >> 6, d = lin & 63;
        t[d][r] = src[r * DHEAD + d];
    }
    __syncthreads();
#pragma unroll
    for (int it = 0; it < 16; it++) {
        int lin = it * 256 + threadIdx.x;
        int dr = lin >> 6, c = lin & 63;
        float v = t[dr][c];
        __nv_bfloat16 hi = __float2bfloat16(v);
        __nv_bfloat16 lo = __float2bfloat16(v - __bfloat162float(hi));
        size_t o = ((size_t)bh * DHEAD + dr) * L_SEQ + l0 + c;
        g_vth[o] = hi;
        g_vtl[o] = lo;
    }
}

// ---------------- tensor-core segment-masked flash attention ----------------
// 128 threads (4 warps) per 64 queries. S = Q'(64x192) K'(64x192)^T via mma,
// softmax in registers, PV = P'(64x192) V'(192x64) with V' = [Vh;Vl;Vh] from V^T.
#define AT_SMEM (3 * 24576)
__global__ __launch_bounds__(128) void attn_mma_kernel(const int* __restrict__ seq_id) {
    extern __shared__ char sm[];
    __shared__ int sidS[64];
    uint32_t qS = smem_u32(sm);
    uint32_t kS = qS + 24576;
    uint32_t vS = kS + 24576;
    int qt = blockIdx.x, hh = blockIdx.y, b = blockIdx.z;
    int bh = b * NHEADS + hh;
    int tid = threadIdx.x, wid = tid >> 5, lane = tid & 31;
    const int* sid = seq_id + b * L_SEQ;
    int q0 = qt * 64;
    int qmin = sid[q0], qmax = sid[q0 + 63];

    int t_lo = 32, t_hi = -1;
    for (int kt = 0; kt < 32; kt++) {
        int kmin = sid[kt * 64], kmax = sid[kt * 64 + 63];
        if (kmax >= qmin && kmin <= qmax) { if (kt < t_lo) t_lo = kt; t_hi = kt; }
    }

    const char* Qg = (const char*)(g_qp + ((size_t)bh * L_SEQ + q0) * 192);
    const char* Kg = (const char*)(g_kp + (size_t)bh * L_SEQ * 192);
    const __nv_bfloat16* VTh = g_vth + (size_t)bh * DHEAD * L_SEQ;
    const __nv_bfloat16* VTl = g_vtl + (size_t)bh * DHEAD * L_SEQ;

    // load Q' + K'(t_lo) + sid(t_lo)
#pragma unroll
    for (int it = 0; it < 12; it++) {
        int lin = it * 128 + tid;
        int row = lin / 24, c8 = lin % 24;
        uint32_t so = (uint32_t)(row * 384 + ((c8 ^ (row & 7)) * 16));
        CP_ASYNC16(qS + so, Qg + row * 384 + c8 * 16);
        CP_ASYNC16(kS + so, Kg + (size_t)(t_lo * 64 + row) * 384 + c8 * 16);
    }
    if (tid < 64) sidS[tid] = sid[t_lo * 64 + tid];
    CP_COMMIT();

    int r0 = lane >> 2;
    int qrow0 = q0 + wid * 16 + r0, qrow1 = qrow0 + 8;
    int sq0 = sid[qrow0], sq1 = sid[qrow1];

    float o[8][4];
#pragma unroll
    for (int i = 0; i < 8; i++)
#pragma unroll
        for (int j = 0; j < 4; j++) o[i][j] = 0.f;
    float m0 = -1e30f, m1 = -1e30f, l0s = 0.f, l1s = 0.f;

    CP_WAIT(0);
    __syncthreads();

    // hoist Q fragments (qS is never rewritten)
    uint32_t qf[12][4];
#pragma unroll
    for (int kc = 0; kc < 12; kc++) {
        int row = wid * 16 + (lane & 15);
        int c8 = kc * 2 + (lane >> 4);
        ldm_x4(qf[kc], qS + row * 384 + ((c8 ^ (row & 7)) * 16));
    }

    for (int t = t_lo; t <= t_hi; t++) {
        int k0 = t * 64;
        // prefetch V'(t): rows = d, c8 0-7 Vh, 8-15 Vl, 16-23 Vh (overlaps S compute)
#pragma unroll
        for (int it = 0; it < 12; it++) {
            int lin = it * 128 + tid;
            int row = lin / 24, c8 = lin % 24;
            uint32_t so = (uint32_t)(row * 384 + ((c8 ^ (row & 7)) * 16));
            const __nv_bfloat16* src = (c8 >= 8 && c8 < 16) ? VTl : VTh;
            CP_ASYNC16(vS + so, (const char*)(src + (size_t)row * L_SEQ + k0) + (c8 & 7) * 16);
        }
        CP_COMMIT();

        // ---- S = Q' K'^T ----
        float sc[8][4];
#pragma unroll
        for (int i = 0; i < 8; i++)
#pragma unroll
            for (int j = 0; j < 4; j++) sc[i][j] = 0.f;
#pragma unroll
        for (int kc = 0; kc < 12; kc++) {
#pragma unroll
            for (int nb = 0; nb < 4; nb++) {
                uint32_t bb[4];
                int row = nb * 16 + ((lane >> 4) & 1) * 8 + (lane & 7);
                int c8 = kc * 2 + ((lane >> 3) & 1);
                ldm_x4(bb, kS + row * 384 + ((c8 ^ (row & 7)) * 16));
                mma_bf16(sc[2 * nb], qf[kc], bb[0], bb[1]);
                mma_bf16(sc[2 * nb + 1], qf[kc], bb[2], bb[3]);
            }
        }

        // ---- mask + online softmax ----
        float mt0 = m0, mt1 = m1;
#pragma unroll
        for (int ni = 0; ni < 8; ni++) {
            int kb = 8 * ni + 2 * (lane & 3);
            int ks0 = sidS[kb], ks1 = sidS[kb + 1];
            if (ks0 != sq0) sc[ni][0] = -1e30f;
            if (ks1 != sq0) sc[ni][1] = -1e30f;
            if (ks0 != sq1) sc[ni][2] = -1e30f;
            if (ks1 != sq1) sc[ni][3] = -1e30f;
            mt0 = fmaxf(mt0, fmaxf(sc[ni][0], sc[ni][1]));
            mt1 = fmaxf(mt1, fmaxf(sc[ni][2], sc[ni][3]));
        }
        mt0 = fmaxf(mt0, __shfl_xor_sync(0xffffffffu, mt0, 1));
        mt0 = fmaxf(mt0, __shfl_xor_sync(0xffffffffu, mt0, 2));
        mt1 = fmaxf(mt1, __shfl_xor_sync(0xffffffffu, mt1, 1));
        mt1 = fmaxf(mt1, __shfl_xor_sync(0xffffffffu, mt1, 2));
        float al0 = expf(m0 - mt0), al1 = expf(m1 - mt1);
        m0 = mt0; m1 = mt1;
        l0s *= al0; l1s *= al1;
#pragma unroll
        for (int ni = 0; ni < 8; ni++) {
            o[ni][0] *= al0; o[ni][1] *= al0;
            o[ni][2] *= al1; o[ni][3] *= al1;
        }
        // p = exp(s - m), bf16 hi/lo, pack into A-fragments (C-frag layout == A-frag layout)
        uint32_t ah[4][4], alr[4][4];
#pragma unroll
        for (int ni = 0; ni < 8; ni++) {
            float p0 = sc[ni][0] > -1e29f ? expf(sc[ni][0] - mt0) : 0.f;
            float p1 = sc[ni][1] > -1e29f ? expf(sc[ni][1] - mt0) : 0.f;
            float p2 = sc[ni][2] > -1e29f ? expf(sc[ni][2] - mt1) : 0.f;
            float p3 = sc[ni][3] > -1e29f ? expf(sc[ni][3] - mt1) : 0.f;
            l0s += p0 + p1; l1s += p2 + p3;
            float h0 = __bfloat162float(__float2bfloat16(p0));
            float h1 = __bfloat162float(__float2bfloat16(p1));
            float h2 = __bfloat162float(__float2bfloat16(p2));
            float h3 = __bfloat162float(__float2bfloat16(p3));
            int kc = ni >> 1;
            if ((ni & 1) == 0) {
                ah[kc][0] = pack_bf16(h0, h1);
                ah[kc][1] = pack_bf16(h2, h3);
                alr[kc][0] = pack_bf16(p0 - h0, p1 - h1);
                alr[kc][1] = pack_bf16(p2 - h2, p3 - h3);
            } else {
                ah[kc][2] = pack_bf16(h0, h1);
                ah[kc][3] = pack_bf16(h2, h3);
                alr[kc][2] = pack_bf16(p0 - h0, p1 - h1);
                alr[kc][3] = pack_bf16(p2 - h2, p3 - h3);
            }
        }

        CP_WAIT(0);          // V' ready; all warps past K' reads
        __syncthreads();

        // prefetch next K' + sid (overlaps PV compute)
        if (t < t_hi) {
#pragma unroll
            for (int it = 0; it < 12; it++) {
                int lin = it * 128 + tid;
                int row = lin / 24, c8 = lin % 24;
                uint32_t so = (uint32_t)(row * 384 + ((c8 ^ (row & 7)) * 16));
                CP_ASYNC16(kS + so, Kg + (size_t)((t + 1) * 64 + row) * 384 + c8 * 16);
            }
            if (tid < 64) sidS[tid] = sid[(t + 1) * 64 + tid];
            CP_COMMIT();
        }

        // ---- PV: o += P' V' ----
#pragma unroll
        for (int kc = 0; kc < 12; kc++) {
            const uint32_t* A = (kc < 4) ? ah[kc] : (kc < 8) ? ah[kc - 4] : alr[kc - 8];
#pragma unroll
            for (int nb = 0; nb < 4; nb++) {
                uint32_t bb[4];
                int row = nb * 16 + ((lane >> 4) & 1) * 8 + (lane & 7);
                int c8 = kc * 2 + ((lane >> 3) & 1);
                ldm_x4(bb, vS + row * 384 + ((c8 ^ (row & 7)) * 16));
                mma_bf16(o[2 * nb], A, bb[0], bb[1]);
                mma_bf16(o[2 * nb + 1], A, bb[2], bb[3]);
            }
        }

        CP_WAIT(0);
        __syncthreads();
    }

    // ---- epilogue: normalize, write ctx' triple ----
    l0s += __shfl_xor_sync(0xffffffffu, l0s, 1);
    l0s += __shfl_xor_sync(0xffffffffu, l0s, 2);
    l1s += __shfl_xor_sync(0xffffffffu, l1s, 1);
    l1s += __shfl_xor_sync(0xffffffffu, l1s, 2);
    float inv0 = 1.f / l0s, inv1 = 1.f / l1s;
    size_t tok0 = ((size_t)b * L_SEQ + qrow0) * KP + hh * DHEAD;
    size_t tok1 = ((size_t)b * L_SEQ + qrow1) * KP + hh * DHEAD;
#pragma unroll
    for (int ni = 0; ni < 8; ni++) {
        int d = 8 * ni + 2 * (lane & 3);
#pragma unroll
        for (int j = 0; j < 2; j++) {
            float v0 = o[ni][j] * inv0;
            __nv_bfloat16 h = __float2bfloat16(v0);
            __nv_bfloat16 lo = __float2bfloat16(v0 - __bfloat162float(h));
            g_cp[tok0 + d + j] = h;
            g_cp[tok0 + DMODEL + d + j] = h;
            g_cp[tok0 + 2 * DMODEL + d + j] = lo;
            float v1 = o[ni][j + 2] * inv1;
            __nv_bfloat16 h1 = __float2bfloat16(v1);
            __nv_bfloat16 lo1 = __float2bfloat16(v1 - __bfloat162float(h1));
            g_cp[tok1 + d + j] = h1;
            g_cp[tok1 + DMODEL + d + j] = h1;
            g_cp[tok1 + 2 * DMODEL + d + j] = lo1;
        }
    }
}

// ---------------- launch ----------------
extern "C" void kernel_launch(void* const* d_in, const int* in_sizes, int n_in,
                              void* d_out, int out_size) {
    const float* x      = (const float*)d_in[0];
    const int*   seq_id = (const int*)d_in[1];
    const float* ln1_w  = (const float*)d_in[2];
    const float* ln1_b  = (const float*)d_in[3];
    const float* w_qkv  = (const float*)d_in[4];
    const float* q_ln_w = (const float*)d_in[5];
    const float* k_ln_w = (const float*)d_in[6];
    const float* w_out  = (const float*)d_in[7];
    float* out = (float*)d_out;
    (void)in_sizes; (void)n_in; (void)out_size;

    void *p_hq = nullptr, *p_wq = nullptr, *p_cp = nullptr, *p_wo = nullptr, *p_qkv = nullptr;
    cudaGetSymbolAddress(&p_hq, g_hq);
    cudaGetSymbolAddress(&p_wq, g_wqkvp);
    cudaGetSymbolAddress(&p_cp, g_cp);
    cudaGetSymbolAddress(&p_wo, g_woutp);
    cudaGetSymbolAddress(&p_qkv, g_qkv);

    static const int GEMM_SMEM = 64 * 1024;
    cudaFuncSetAttribute(bf16_gemm_kernel,
                         cudaFuncAttributeMaxDynamicSharedMemorySize, GEMM_SMEM);
    cudaFuncSetAttribute(attn_mma_kernel,
                         cudaFuncAttributeMaxDynamicSharedMemorySize, AT_SMEM);

    rope_table_kernel<<<64, 1024>>>();
    transpose_split_kernel<<<dim3(3 * DMODEL / 32, DMODEL / 32), 256>>>(
        w_qkv, (__nv_bfloat16*)p_wq, 3 * DMODEL);
    transpose_split_kernel<<<dim3(DMODEL / 32, DMODEL / 32), 256>>>(
        w_out, (__nv_bfloat16*)p_wo, DMODEL);
    ln1_kernel<<<TOKENS, 256>>>(x, ln1_w, ln1_b);

    bf16_gemm_kernel<<<dim3(3 * DMODEL / GBN, TOKENS / GBM), 256, GEMM_SMEM>>>(
        (const __nv_bfloat16*)p_hq, (const __nv_bfloat16*)p_wq, (float*)p_qkv, 3 * DMODEL);

    qk_ln_rope_kernel<<<TOKENS, 256>>>(q_ln_w, k_ln_w);
    vt_kernel<<<dim3(L_SEQ / 64, NBH), 256>>>();
    attn_mma_kernel<<<dim3(L_SEQ / 64, NHEADS, BATCH), 128, AT_SMEM>>>(seq_id);

    bf16_gemm_kernel<<<dim3(DMODEL / GBN, TOKENS / GBM), 256, GEMM_SMEM>>>(
        (const __nv_bfloat16*)p_cp, (const __nv_bfloat16*)p_wo, out, DMODEL);
}